// round 8
// baseline (speedup 1.0000x reference)
#include <cuda_runtime.h>
#include <cuda_fp16.h>
#include <cstdint>

namespace {

constexpr int B_ = 8, H_ = 64, W_ = 64, C_ = 128, N_ = 9, F_ = 256;
constexpr int THREADS = 256;
constexpr int NCHUNK  = N_ * (C_ / 32);   // 36 chunks of K=32
constexpr int PADP    = 20;               // A stride in b32 pairs (16 data + 4 pad)

// dynamic smem layout (b32 units)
constexpr int A_SZ    = 64 * PADP;        // 1280 words per A buffer
constexpr int W_SZ    = 32 * 32 * 4;      // 4096 words per W buffer [ft][lane][ks*2+j]
constexpr int CR_SZ   = 4 * 256 * 4;      // 4096 words per corner staging buffer [corner][tid][4w]
constexpr int A0_OFF  = 0;
constexpr int A1_OFF  = A_SZ;
constexpr int W0_OFF  = 2 * A_SZ;
constexpr int W1_OFF  = 2 * A_SZ + W_SZ;
constexpr int CR0_OFF = 2 * A_SZ + 2 * W_SZ;
constexpr int CR1_OFF = CR0_OFF + CR_SZ;
constexpr int CRD_OFF = CR0_OFF + 2 * CR_SZ;
constexpr int SMEM_WORDS = CRD_OFF + 4 * N_ * 64;
constexpr int SMEM_BYTES = SMEM_WORDS * 4;    // 84992 B

// Faithful reproduction of reference (2,3,3)->(9,2) reshape order
__constant__ int c_iy[9] = {0, 0, 1, 2, 2, 1, 0, 2, 1};
__constant__ int c_ix[9] = {0, 1, 1, 2, 0, 2, 1, 0, 2};

// fp16 copy of x: [b][y][x][c]
__device__ __half g_xh[B_ * H_ * W_ * C_];
// W fragment image (fp16 pairs): [n][cc][ft(32)][lane(32)][ks(2)][j(2)]
__device__ uint32_t g_Wimg[N_ * 4 * W_SZ];

__device__ __forceinline__ uint32_t pack2(float a, float b) {
    __half2 h = __floats2half2_rn(a, b);
    return *reinterpret_cast<uint32_t*>(&h);
}
__device__ __forceinline__ float2 up2(uint32_t u) {
    return __half22float2(*reinterpret_cast<__half2*>(&u));
}
__device__ __forceinline__ uint32_t smem_u32(const void* p) {
    uint32_t a;
    asm("{ .reg .u64 t; cvta.to.shared.u64 t, %1; cvt.u32.u64 %0, t; }" : "=r"(a) : "l"(p));
    return a;
}
__device__ __forceinline__ void cp_async16(uint32_t dst, const void* src) {
    asm volatile("cp.async.ca.shared.global [%0], [%1], 16;" :: "r"(dst), "l"(src) : "memory");
}
__device__ __forceinline__ void cp_commit() {
    asm volatile("cp.async.commit_group;" ::: "memory");
}
template <int N>
__device__ __forceinline__ void cp_wait() {
    asm volatile("cp.async.wait_group %0;" :: "n"(N) : "memory");
}
__device__ __forceinline__ void mma_f16(float* c, const uint32_t* a, uint32_t b0, uint32_t b1) {
    asm volatile(
        "mma.sync.aligned.m16n8k16.row.col.f32.f16.f16.f32 "
        "{%0,%1,%2,%3}, {%4,%5,%6,%7}, {%8,%9}, {%0,%1,%2,%3};"
        : "+f"(c[0]), "+f"(c[1]), "+f"(c[2]), "+f"(c[3])
        : "r"(a[0]), "r"(a[1]), "r"(a[2]), "r"(a[3]), "r"(b0), "r"(b1));
}
__device__ __forceinline__ void ldsm_x4(uint32_t* r, uint32_t addr) {
    asm volatile("ldmatrix.sync.aligned.m8n8.x4.shared.b16 {%0,%1,%2,%3}, [%4];"
                 : "=r"(r[0]), "=r"(r[1]), "=r"(r[2]), "=r"(r[3]) : "r"(addr));
}

// lerp 8 channels (4 half2 words) in fp32, repack to half2
__device__ __forceinline__ uint4 lerp8(uint4 lt, uint4 rt, uint4 lb, uint4 rb,
                                       float fy, float fx) {
    uint4 o;
    uint32_t* pl = (uint32_t*)&lt;
    uint32_t* pr = (uint32_t*)&rt;
    uint32_t* ql = (uint32_t*)&lb;
    uint32_t* qr = (uint32_t*)&rb;
    uint32_t* po = (uint32_t*)&o;
    #pragma unroll
    for (int w = 0; w < 4; w++) {
        float2 flt = up2(pl[w]), frt = up2(pr[w]);
        float2 flb = up2(ql[w]), frb = up2(qr[w]);
        float t0 = flt.x + (frt.x - flt.x) * fy;
        float b0 = flb.x + (frb.x - flb.x) * fy;
        float t1 = flt.y + (frt.y - flt.y) * fy;
        float b1 = flb.y + (frb.y - flb.y) * fy;
        po[w] = pack2(t0 + (b0 - t0) * fx, t1 + (b1 - t1) * fx);
    }
    return o;
}

// ---------------- x -> fp16 pre-kernel ----------------
__global__ void xh_kernel(const float* __restrict__ x) {
    int i = (blockIdx.x * 256 + threadIdx.x) * 4;
    float4 v = *(const float4*)(x + i);
    uint2 o;
    o.x = pack2(v.x, v.y);
    o.y = pack2(v.z, v.w);
    *(uint2*)(g_xh + i) = o;
}

// ---------------- W fragment-image pre-kernel (fp16) ----------------
__global__ void wimg_kernel(const float* __restrict__ Wt) {
    int idx = blockIdx.x * 256 + threadIdx.x;   // 0 .. N_*4*W_SZ-1
    int j    = idx & 1;
    int ks   = (idx >> 1) & 1;
    int lane = (idx >> 2) & 31;
    int ft   = (idx >> 7) & 31;
    int cc   = (idx >> 12) & 3;
    int n    = idx >> 14;
    int gq = lane >> 2, tq = lane & 3;
    int f  = ft * 8 + gq;
    int c0 = cc * 32 + ks * 16 + j * 8 + tq * 2;
    float w0 = Wt[((size_t)n * C_ + c0) * F_ + f];
    float w1 = Wt[((size_t)n * C_ + c0 + 1) * F_ + f];
    g_Wimg[idx] = pack2(w0, w1);
}

// ---------------- main fused kernel ----------------
__global__ __launch_bounds__(THREADS, 2)
void deform_mma_kernel(const float* __restrict__ offs,
                       const float* __restrict__ bias,
                       float* __restrict__ out) {
    extern __shared__ float smf[];
    uint32_t* A_buf[2]  = { (uint32_t*)smf + A0_OFF, (uint32_t*)smf + A1_OFF };
    uint32_t* W_buf[2]  = { (uint32_t*)smf + W0_OFF, (uint32_t*)smf + W1_OFF };
    uint32_t* CR_buf[2] = { (uint32_t*)smf + CR0_OFF, (uint32_t*)smf + CR1_OFF };
    int*   s_y0 = (int*)smf + CRD_OFF;
    int*   s_x0 = s_y0 + N_ * 64;
    float* s_fy = (float*)(s_x0 + N_ * 64);
    float* s_fx = s_fy + N_ * 64;

    const uint32_t w_smem[2]  = { smem_u32(W_buf[0]), smem_u32(W_buf[1]) };
    const uint32_t cr_smem[2] = { smem_u32(CR_buf[0]), smem_u32(CR_buf[1]) };
    const uint32_t a_smem[2]  = { smem_u32(A_buf[0]), smem_u32(A_buf[1]) };

    const int tid  = threadIdx.x;
    const int wid  = tid >> 5;
    const int lane = tid & 31;
    const int wr   = wid >> 2;        // warp row (0..1): m base = wr*32
    const int wc   = wid & 3;         // warp col (0..3): f base = wc*64
    const int gq   = lane >> 2;
    const int tq   = lane & 3;

    // ldmatrix lane offset within the warp's A block (words)
    const int lrow = (lane & 7) + ((lane >> 3) & 1) * 8;
    const int lcol = (lane >> 4) * 4;
    const uint32_t a_frag_off = (uint32_t)(((wr * 32 + lrow) * PADP + lcol) * 4);

    const int blk = blockIdx.x;       // b*64 + h
    const int b   = blk >> 6;
    const int h   = blk & 63;
    const __half* img = g_xh + (size_t)b * H_ * W_ * C_;

    const int c8  = tid & 3;          // 8-channel slice within 32-ch chunk
    const int pix = tid >> 2;         // 0..63

    // ---- precompute coordinates for all 9 taps (64 pixels each) ----
    for (int e = tid; e < N_ * 64; e += THREADS) {
        const int n  = e >> 6;
        const int ww = e & 63;
        const float* orow = offs + (((size_t)blk * 64 + ww) * (2 * N_));
        float cy = (float)(h - 1 + c_iy[n]) + orow[2 * n];
        float cx = (float)(ww - 1 + c_ix[n]) + orow[2 * n + 1];
        cy = fminf(fmaxf(cy, 0.0f), 63.0f);
        cx = fminf(fmaxf(cx, 0.0f), 63.0f);
        float y0f = floorf(cy);
        float x0f = floorf(cx);
        s_y0[e] = (int)y0f;
        s_x0[e] = (int)x0f;
        s_fy[e] = cy - y0f;
        s_fx[e] = cx - x0f;
    }
    __syncthreads();

    // issue corner gathers for chunk kk into CR_buf[kk&1]
    auto issue_corners = [&](int kk) {
        const int n2  = kk >> 2;
        const int cc2 = kk & 3;
        const int e   = n2 * 64 + pix;
        const int y0  = s_y0[e];
        const int x0  = s_x0[e];
        const int y1  = min(y0 + 1, 63);
        const int x1  = min(x0 + 1, 63);
        const int c_off = cc2 * 32 + c8 * 8;
        const uint32_t dst = cr_smem[kk & 1] + (uint32_t)tid * 16u;
        cp_async16(dst,             img + ((y0 * 64 + x0) << 7) + c_off);
        cp_async16(dst + 4096u,     img + ((y1 * 64 + x0) << 7) + c_off);
        cp_async16(dst + 8192u,     img + ((y0 * 64 + x1) << 7) + c_off);
        cp_async16(dst + 12288u,    img + ((y1 * 64 + x1) << 7) + c_off);
    };
    // issue W tile copy for chunk kk into W_buf[kk&1]
    auto issue_w = [&](int kk) {
        const int n2  = kk >> 2;
        const int cc2 = kk & 3;
        const uint32_t* wsrc = g_Wimg + (size_t)(n2 * 4 + cc2) * W_SZ;
        const uint32_t wdst = w_smem[kk & 1];
        #pragma unroll
        for (int i = 0; i < 4; i++) {
            int o = i * THREADS + tid;
            cp_async16(wdst + (uint32_t)o * 16u, wsrc + o * 4);
        }
    };
    // lerp staged corners of chunk kk -> A_buf[kk&1]
    auto lerp_chunk = [&](int kk) {
        const int n2 = kk >> 2;
        const int e  = n2 * 64 + pix;
        const uint32_t* cr = CR_buf[kk & 1] + tid * 4;
        uint4 lt = *(const uint4*)(cr);
        uint4 rt = *(const uint4*)(cr + 1024);
        uint4 lb = *(const uint4*)(cr + 2048);
        uint4 rb = *(const uint4*)(cr + 3072);
        *(uint4*)(A_buf[kk & 1] + pix * PADP + c8 * 4) =
            lerp8(lt, rt, lb, rb, s_fy[e], s_fx[e]);
    };

    float acc[2][8][4];
    #pragma unroll
    for (int mi = 0; mi < 2; mi++)
        #pragma unroll
        for (int ni = 0; ni < 8; ni++)
            #pragma unroll
            for (int r = 0; r < 4; r++) acc[mi][ni][r] = 0.0f;

    // ---- prologue: groups Gc(0), Gc(1), Gw(0) ----
    issue_corners(0); cp_commit();
    issue_corners(1); cp_commit();
    issue_w(0);       cp_commit();
    cp_wait<1>();      // Gc(0), Gc(1) done (Gw(0) may be pending)
    lerp_chunk(0);     // A(0) into A_buf[0]

    // ---- main pipelined loop ----
    #pragma unroll 1
    for (int it = 0; it < NCHUNK; it++) {
        __syncthreads();   // A(it) visible; W/CR buffer reuse protected

        const int buf = it & 1;

        if (it + 1 < NCHUNK) { issue_w(it + 1); cp_commit(); }
        if (it + 2 < NCHUNK) { issue_corners(it + 2); cp_commit(); }

        // wait so that all groups except those committed THIS iteration are done
        if (it < NCHUNK - 2)       cp_wait<2>();
        else if (it == NCHUNK - 2) cp_wait<1>();
        else                       cp_wait<0>();
        __syncthreads();   // W(it) written by cp.async visible to all warps

        // ---- MMA(it): 2 k-steps of m16n8k16 fp16 ----
        {
            const uint32_t* W_s = W_buf[buf];
            const uint32_t a_base = a_smem[buf] + a_frag_off;
            uint32_t a[2][2][4];   // [ks][mi][reg]
            #pragma unroll
            for (int mi = 0; mi < 2; mi++) {
                ldsm_x4(a[0][mi], a_base + (uint32_t)((mi * 16 * PADP) * 4));
                ldsm_x4(a[1][mi], a_base + (uint32_t)((mi * 16 * PADP + 8) * 4));
            }
            #pragma unroll
            for (int ni = 0; ni < 8; ni++) {
                const int ftl = wc * 8 + ni;
                uint4 bv = *(const uint4*)(W_s + ((ftl * 32) + lane) * 4);
                mma_f16(acc[0][ni], a[0][0], bv.x, bv.y);
                mma_f16(acc[1][ni], a[0][1], bv.x, bv.y);
                mma_f16(acc[0][ni], a[1][0], bv.z, bv.w);
                mma_f16(acc[1][ni], a[1][1], bv.z, bv.w);
            }
        }

        // ---- build A(it+1) from staged corners ----
        if (it + 1 < NCHUNK) lerp_chunk(it + 1);
    }

    // ---- epilogue: add bias, store ----
    #pragma unroll
    for (int mi = 0; mi < 2; mi++) {
        const int row0 = wr * 32 + mi * 16 + gq;
        float* o0 = out + ((size_t)blk * 64 + row0) * F_;
        float* o1 = o0 + 8 * F_;
        #pragma unroll
        for (int ni = 0; ni < 8; ni++) {
            const int f = wc * 64 + ni * 8 + tq * 2;
            const float2 bb = *(const float2*)(bias + f);
            float2 r0, r1;
            r0.x = acc[mi][ni][0] + bb.x;
            r0.y = acc[mi][ni][1] + bb.y;
            r1.x = acc[mi][ni][2] + bb.x;
            r1.y = acc[mi][ni][3] + bb.y;
            *(float2*)(o0 + f) = r0;
            *(float2*)(o1 + f) = r1;
        }
    }
}

}  // namespace

extern "C" void kernel_launch(void* const* d_in, const int* in_sizes, int n_in,
                              void* d_out, int out_size) {
    (void)in_sizes; (void)n_in; (void)out_size;
    const float* x    = (const float*)d_in[0];   // (8,64,64,128)
    const float* offs = (const float*)d_in[1];   // (8,64,64,18)
    const float* Wt   = (const float*)d_in[2];   // (9,128,256)
    const float* bias = (const float*)d_in[3];   // (256,)
    float* out = (float*)d_out;                  // (8,64,64,256)

    cudaFuncSetAttribute(deform_mma_kernel,
                         cudaFuncAttributeMaxDynamicSharedMemorySize, SMEM_BYTES);

    xh_kernel<<<(B_ * H_ * W_ * C_) / (256 * 4), 256>>>(x);
    wimg_kernel<<<(N_ * 4 * W_SZ) / 256, 256>>>(Wt);
    deform_mma_kernel<<<B_ * H_, THREADS, SMEM_BYTES>>>(offs, bias, out);
}

// round 9
// speedup vs baseline: 1.1728x; 1.1728x over previous
#include <cuda_runtime.h>
#include <cuda_fp16.h>
#include <cstdint>

namespace {

constexpr int B_ = 8, H_ = 64, W_ = 64, C_ = 128, N_ = 9, F_ = 256;
constexpr int THREADS = 256;
constexpr int NCHUNK  = N_ * (C_ / 32);   // 36 chunks of K=32
constexpr int PADP    = 20;               // A stride in b32 pairs (16 data + 4 pad)

// dynamic smem layout (b32 units)
constexpr int A_SZ    = 64 * PADP;        // 1280 words per A buffer
constexpr int W_SZ    = 32 * 32 * 4;      // 4096 words per W buffer [ft][lane][ks*2+j]
constexpr int A0_OFF  = 0;
constexpr int A1_OFF  = A_SZ;
constexpr int W0_OFF  = 2 * A_SZ;
constexpr int W1_OFF  = 2 * A_SZ + W_SZ;
constexpr int CRD_OFF = 2 * A_SZ + 2 * W_SZ;
constexpr int SMEM_WORDS = CRD_OFF + 4 * N_ * 64;
constexpr int SMEM_BYTES = SMEM_WORDS * 4;    // 52224 B

// Faithful reproduction of reference (2,3,3)->(9,2) reshape order
__constant__ int c_iy[9] = {0, 0, 1, 2, 2, 1, 0, 2, 1};
__constant__ int c_ix[9] = {0, 1, 1, 2, 0, 2, 1, 0, 2};

// fp16 copy of x: [b][y][x][c]
__device__ __half g_xh[B_ * H_ * W_ * C_];
// W fragment image (fp16 pairs): [n][cc][ft(32)][lane(32)][ks(2)][j(2)]
__device__ uint32_t g_Wimg[N_ * 4 * W_SZ];

__device__ __forceinline__ uint32_t pack2(float a, float b) {
    __half2 h = __floats2half2_rn(a, b);
    return *reinterpret_cast<uint32_t*>(&h);
}
__device__ __forceinline__ float2 up2(uint32_t u) {
    return __half22float2(*reinterpret_cast<__half2*>(&u));
}
__device__ __forceinline__ uint32_t smem_u32(const void* p) {
    uint32_t a;
    asm("{ .reg .u64 t; cvta.to.shared.u64 t, %1; cvt.u32.u64 %0, t; }" : "=r"(a) : "l"(p));
    return a;
}
__device__ __forceinline__ void cp_async16(uint32_t dst, const void* src) {
    asm volatile("cp.async.ca.shared.global [%0], [%1], 16;" :: "r"(dst), "l"(src) : "memory");
}
__device__ __forceinline__ void cp_commit() {
    asm volatile("cp.async.commit_group;" ::: "memory");
}
__device__ __forceinline__ void cp_wait0() {
    asm volatile("cp.async.wait_group 0;" ::: "memory");
}
__device__ __forceinline__ void mma_f16(float* c, const uint32_t* a, uint32_t b0, uint32_t b1) {
    asm volatile(
        "mma.sync.aligned.m16n8k16.row.col.f32.f16.f16.f32 "
        "{%0,%1,%2,%3}, {%4,%5,%6,%7}, {%8,%9}, {%0,%1,%2,%3};"
        : "+f"(c[0]), "+f"(c[1]), "+f"(c[2]), "+f"(c[3])
        : "r"(a[0]), "r"(a[1]), "r"(a[2]), "r"(a[3]), "r"(b0), "r"(b1));
}
__device__ __forceinline__ void ldsm_x4(uint32_t* r, uint32_t addr) {
    asm volatile("ldmatrix.sync.aligned.m8n8.x4.shared.b16 {%0,%1,%2,%3}, [%4];"
                 : "=r"(r[0]), "=r"(r[1]), "=r"(r[2]), "=r"(r[3]) : "r"(addr));
}

// lerp 8 channels (4 half2 words) in fp32, repack to half2
__device__ __forceinline__ uint4 lerp8(uint4 lt, uint4 rt, uint4 lb, uint4 rb,
                                       float fy, float fx) {
    uint4 o;
    uint32_t* pl = (uint32_t*)&lt;
    uint32_t* pr = (uint32_t*)&rt;
    uint32_t* ql = (uint32_t*)&lb;
    uint32_t* qr = (uint32_t*)&rb;
    uint32_t* po = (uint32_t*)&o;
    #pragma unroll
    for (int w = 0; w < 4; w++) {
        float2 flt = up2(pl[w]), frt = up2(pr[w]);
        float2 flb = up2(ql[w]), frb = up2(qr[w]);
        float t0 = flt.x + (frt.x - flt.x) * fy;
        float b0 = flb.x + (frb.x - flb.x) * fy;
        float t1 = flt.y + (frt.y - flt.y) * fy;
        float b1 = flb.y + (frb.y - flb.y) * fy;
        po[w] = pack2(t0 + (b0 - t0) * fx, t1 + (b1 - t1) * fx);
    }
    return o;
}

// ---------------- x -> fp16 pre-kernel (8 floats/thread) ----------------
__global__ void xh_kernel(const float* __restrict__ x) {
    int i = (blockIdx.x * 256 + threadIdx.x) * 8;
    float4 v0 = *(const float4*)(x + i);
    float4 v1 = *(const float4*)(x + i + 4);
    uint4 o;
    o.x = pack2(v0.x, v0.y);
    o.y = pack2(v0.z, v0.w);
    o.z = pack2(v1.x, v1.y);
    o.w = pack2(v1.z, v1.w);
    *(uint4*)(g_xh + i) = o;
}

// ---------------- W fragment-image pre-kernel (fp16) ----------------
__global__ void wimg_kernel(const float* __restrict__ Wt) {
    int idx = blockIdx.x * 256 + threadIdx.x;   // 0 .. N_*4*W_SZ-1
    int j    = idx & 1;
    int ks   = (idx >> 1) & 1;
    int lane = (idx >> 2) & 31;
    int ft   = (idx >> 7) & 31;
    int cc   = (idx >> 12) & 3;
    int n    = idx >> 14;
    int gq = lane >> 2, tq = lane & 3;
    int f  = ft * 8 + gq;
    int c0 = cc * 32 + ks * 16 + j * 8 + tq * 2;
    float w0 = Wt[((size_t)n * C_ + c0) * F_ + f];
    float w1 = Wt[((size_t)n * C_ + c0 + 1) * F_ + f];
    g_Wimg[idx] = pack2(w0, w1);
}

// ---------------- main fused kernel ----------------
__global__ __launch_bounds__(THREADS, 2)
void deform_mma_kernel(const float* __restrict__ offs,
                       const float* __restrict__ bias,
                       float* __restrict__ out) {
    extern __shared__ float smf[];
    uint32_t* A_buf[2] = { (uint32_t*)smf + A0_OFF, (uint32_t*)smf + A1_OFF };
    uint32_t* W_buf[2] = { (uint32_t*)smf + W0_OFF, (uint32_t*)smf + W1_OFF };
    int*   s_y0 = (int*)smf + CRD_OFF;
    int*   s_x0 = s_y0 + N_ * 64;
    float* s_fy = (float*)(s_x0 + N_ * 64);
    float* s_fx = s_fy + N_ * 64;

    const uint32_t w_smem_u32[2] = { smem_u32(W_buf[0]), smem_u32(W_buf[1]) };
    const uint32_t a_smem_u32[2] = { smem_u32(A_buf[0]), smem_u32(A_buf[1]) };

    const int tid  = threadIdx.x;
    const int wid  = tid >> 5;
    const int lane = tid & 31;
    const int wr   = wid >> 2;        // warp row (0..1): m base = wr*32
    const int wc   = wid & 3;         // warp col (0..3): f base = wc*64
    const int gq   = lane >> 2;
    const int tq   = lane & 3;

    // ldmatrix lane offset within the warp's A block (words)
    const int lrow = (lane & 7) + ((lane >> 3) & 1) * 8;
    const int lcol = (lane >> 4) * 4;
    const uint32_t a_frag_off = (uint32_t)(((wr * 32 + lrow) * PADP + lcol) * 4);

    const int blk = blockIdx.x;       // b*64 + h
    const int b   = blk >> 6;
    const int h   = blk & 63;
    const __half* img = g_xh + (size_t)b * H_ * W_ * C_;

    const int c8  = tid & 3;          // 8-channel slice within 32-ch chunk
    const int pix = tid >> 2;         // 0..63

    // phase decorrelation: each CTA starts the (commutative) K loop at its own chunk
    const int s0 = blk % NCHUNK;

    // ---- precompute coordinates for all 9 taps (64 pixels each) ----
    for (int e = tid; e < N_ * 64; e += THREADS) {
        const int n  = e >> 6;
        const int ww = e & 63;
        const float* orow = offs + (((size_t)blk * 64 + ww) * (2 * N_));
        float cy = (float)(h - 1 + c_iy[n]) + orow[2 * n];
        float cx = (float)(ww - 1 + c_ix[n]) + orow[2 * n + 1];
        cy = fminf(fmaxf(cy, 0.0f), 63.0f);
        cx = fminf(fmaxf(cx, 0.0f), 63.0f);
        float y0f = floorf(cy);
        float x0f = floorf(cx);
        s_y0[e] = (int)y0f;
        s_x0[e] = (int)x0f;
        s_fy[e] = cy - y0f;
        s_fx[e] = cx - x0f;
    }
    __syncthreads();

    float acc[2][8][4];
    #pragma unroll
    for (int mi = 0; mi < 2; mi++)
        #pragma unroll
        for (int ni = 0; ni < 8; ni++)
            #pragma unroll
            for (int r = 0; r < 4; r++) acc[mi][ni][r] = 0.0f;

    // ---- prologue: stage chunk s0 into buffer 0 ----
    {
        const int n0  = s0 >> 2;
        const int cc0 = s0 & 3;
        const uint32_t* wsrc = g_Wimg + (size_t)s0 * W_SZ;
        #pragma unroll
        for (int i = 0; i < 4; i++) {
            int o = i * THREADS + tid;
            cp_async16(w_smem_u32[0] + o * 16u, wsrc + o * 4);
        }
        cp_commit();
        const int c_off = cc0 * 32 + c8 * 8;
        const int e  = n0 * 64 + pix;
        const int y0 = s_y0[e];
        const int x0 = s_x0[e];
        const int y1 = min(y0 + 1, 63);
        const int x1 = min(x0 + 1, 63);
        uint4 vlt = *(const uint4*)(img + ((y0 * 64 + x0) << 7) + c_off);
        uint4 vrt = *(const uint4*)(img + ((y1 * 64 + x0) << 7) + c_off);
        uint4 vlb = *(const uint4*)(img + ((y0 * 64 + x1) << 7) + c_off);
        uint4 vrb = *(const uint4*)(img + ((y1 * 64 + x1) << 7) + c_off);
        *(uint4*)(A_buf[0] + pix * PADP + c8 * 4) =
            lerp8(vlt, vrt, vlb, vrb, s_fy[e], s_fx[e]);
    }

    // ---- main pipelined loop (chunk order rotated by s0) ----
    int kn = s0;   // chunk id of iteration it
    #pragma unroll 1
    for (int it = 0; it < NCHUNK; it++) {
        cp_wait0();
        __syncthreads();

        const int buf  = it & 1;
        const int nbuf = buf ^ 1;
        const bool more = (it + 1 < NCHUNK);
        int kk2 = kn + 1;
        if (kk2 == NCHUNK) kk2 = 0;   // next chunk id

        uint4 vlt, vrt, vlb, vrb;
        float pfy, pfx;

        if (more) {
            const int n2  = kk2 >> 2;
            const int cc2 = kk2 & 3;
            const uint32_t* wsrc = g_Wimg + (size_t)kk2 * W_SZ;
            #pragma unroll
            for (int i = 0; i < 4; i++) {
                int o = i * THREADS + tid;
                cp_async16(w_smem_u32[nbuf] + o * 16u, wsrc + o * 4);
            }
            cp_commit();
            const int c_off = cc2 * 32 + c8 * 8;
            const int e  = n2 * 64 + pix;
            const int y0 = s_y0[e];
            const int x0 = s_x0[e];
            pfy = s_fy[e];
            pfx = s_fx[e];
            const int y1 = min(y0 + 1, 63);
            const int x1 = min(x0 + 1, 63);
            vlt = *(const uint4*)(img + ((y0 * 64 + x0) << 7) + c_off);
            vrt = *(const uint4*)(img + ((y1 * 64 + x0) << 7) + c_off);
            vlb = *(const uint4*)(img + ((y0 * 64 + x1) << 7) + c_off);
            vrb = *(const uint4*)(img + ((y1 * 64 + x1) << 7) + c_off);
        }

        // ---- MMA(it): 2 k-steps of m16n8k16 fp16 ----
        {
            const uint32_t* W_s = W_buf[buf];
            const uint32_t a_base = a_smem_u32[buf] + a_frag_off;
            uint32_t a[2][2][4];   // [ks][mi][reg]
            #pragma unroll
            for (int mi = 0; mi < 2; mi++) {
                ldsm_x4(a[0][mi], a_base + (uint32_t)((mi * 16 * PADP) * 4));
                ldsm_x4(a[1][mi], a_base + (uint32_t)((mi * 16 * PADP + 8) * 4));
            }
            #pragma unroll
            for (int ni = 0; ni < 8; ni++) {
                const int ftl = wc * 8 + ni;
                uint4 bv = *(const uint4*)(W_s + ((ftl * 32) + lane) * 4);
                mma_f16(acc[0][ni], a[0][0], bv.x, bv.y);
                mma_f16(acc[1][ni], a[0][1], bv.x, bv.y);
                mma_f16(acc[0][ni], a[1][0], bv.z, bv.w);
                mma_f16(acc[1][ni], a[1][1], bv.z, bv.w);
            }
        }

        // ---- finish A(it+1): lerp + pack + STS ----
        if (more) {
            *(uint4*)(A_buf[nbuf] + pix * PADP + c8 * 4) =
                lerp8(vlt, vrt, vlb, vrb, pfy, pfx);
        }

        kn = kk2;
    }

    // ---- epilogue: add bias, store ----
    #pragma unroll
    for (int mi = 0; mi < 2; mi++) {
        const int row0 = wr * 32 + mi * 16 + gq;
        float* o0 = out + ((size_t)blk * 64 + row0) * F_;
        float* o1 = o0 + 8 * F_;
        #pragma unroll
        for (int ni = 0; ni < 8; ni++) {
            const int f = wc * 64 + ni * 8 + tq * 2;
            const float2 bb = *(const float2*)(bias + f);
            float2 r0, r1;
            r0.x = acc[mi][ni][0] + bb.x;
            r0.y = acc[mi][ni][1] + bb.y;
            r1.x = acc[mi][ni][2] + bb.x;
            r1.y = acc[mi][ni][3] + bb.y;
            *(float2*)(o0 + f) = r0;
            *(float2*)(o1 + f) = r1;
        }
    }
}

}  // namespace

extern "C" void kernel_launch(void* const* d_in, const int* in_sizes, int n_in,
                              void* d_out, int out_size) {
    (void)in_sizes; (void)n_in; (void)out_size;
    const float* x    = (const float*)d_in[0];   // (8,64,64,128)
    const float* offs = (const float*)d_in[1];   // (8,64,64,18)
    const float* Wt   = (const float*)d_in[2];   // (9,128,256)
    const float* bias = (const float*)d_in[3];   // (256,)
    float* out = (float*)d_out;                  // (8,64,64,256)

    cudaFuncSetAttribute(deform_mma_kernel,
                         cudaFuncAttributeMaxDynamicSharedMemorySize, SMEM_BYTES);

    xh_kernel<<<(B_ * H_ * W_ * C_) / (256 * 8), 256>>>(x);
    wimg_kernel<<<(N_ * 4 * W_SZ) / 256, 256>>>(Wt);
    deform_mma_kernel<<<B_ * H_, THREADS, SMEM_BYTES>>>(offs, bias, out);
}

// round 10
// speedup vs baseline: 1.1929x; 1.0172x over previous
#include <cuda_runtime.h>
#include <cuda_fp16.h>
#include <cstdint>

namespace {

constexpr int B_ = 8, H_ = 64, W_ = 64, C_ = 128, N_ = 9, F_ = 256;
constexpr int THREADS = 256;
constexpr int NSTAGE  = 18;               // stages of K=64 (2 chunks of 32)
constexpr int PADP    = 36;               // A stride in b32 pairs (32 data + 4 pad)

// dynamic smem layout (b32 units)
constexpr int A_SZ    = 64 * PADP;        // 2304 words per A buffer (64 px x 64 ch)
constexpr int W_CH    = 32 * 32 * 4;      // 4096 words per chunk W image
constexpr int W_SZ    = 2 * W_CH;         // 8192 words per W stage buffer
constexpr int A0_OFF  = 0;
constexpr int A1_OFF  = A_SZ;
constexpr int W0_OFF  = 2 * A_SZ;
constexpr int W1_OFF  = 2 * A_SZ + W_SZ;
constexpr int C4_OFF  = 2 * A_SZ + 2 * W_SZ;       // int4 per (tap,pixel): 576*4 words
constexpr int FY_OFF  = C4_OFF + 4 * N_ * 64;
constexpr int FX_OFF  = FY_OFF + N_ * 64;
constexpr int SMEM_WORDS = FX_OFF + N_ * 64;
constexpr int SMEM_BYTES = SMEM_WORDS * 4;          // ~97.8 KB

// Faithful reproduction of reference (2,3,3)->(9,2) reshape order
__constant__ int c_iy[9] = {0, 0, 1, 2, 2, 1, 0, 2, 1};
__constant__ int c_ix[9] = {0, 1, 1, 2, 0, 2, 1, 0, 2};

// fp16 copy of x: [b][y][x][c]
__device__ __half g_xh[B_ * H_ * W_ * C_];
// W fragment image (fp16 pairs): [k(36)][ft(32)][lane(32)][ks(2)][j(2)]
__device__ uint32_t g_Wimg[36 * W_CH];

__device__ __forceinline__ uint32_t pack2(float a, float b) {
    __half2 h = __floats2half2_rn(a, b);
    return *reinterpret_cast<uint32_t*>(&h);
}
__device__ __forceinline__ uint32_t smem_u32(const void* p) {
    uint32_t a;
    asm("{ .reg .u64 t; cvta.to.shared.u64 t, %1; cvt.u32.u64 %0, t; }" : "=r"(a) : "l"(p));
    return a;
}
__device__ __forceinline__ void cp_async16(uint32_t dst, const void* src) {
    asm volatile("cp.async.ca.shared.global [%0], [%1], 16;" :: "r"(dst), "l"(src) : "memory");
}
__device__ __forceinline__ void cp_commit() {
    asm volatile("cp.async.commit_group;" ::: "memory");
}
__device__ __forceinline__ void cp_wait0() {
    asm volatile("cp.async.wait_group 0;" ::: "memory");
}
__device__ __forceinline__ void mma_f16(float* c, const uint32_t* a, uint32_t b0, uint32_t b1) {
    asm volatile(
        "mma.sync.aligned.m16n8k16.row.col.f32.f16.f16.f32 "
        "{%0,%1,%2,%3}, {%4,%5,%6,%7}, {%8,%9}, {%0,%1,%2,%3};"
        : "+f"(c[0]), "+f"(c[1]), "+f"(c[2]), "+f"(c[3])
        : "r"(a[0]), "r"(a[1]), "r"(a[2]), "r"(a[3]), "r"(b0), "r"(b1));
}
__device__ __forceinline__ void ldsm_x4(uint32_t* r, uint32_t addr) {
    asm volatile("ldmatrix.sync.aligned.m8n8.x4.shared.b16 {%0,%1,%2,%3}, [%4];"
                 : "=r"(r[0]), "=r"(r[1]), "=r"(r[2]), "=r"(r[3]) : "r"(addr));
}

// half2 bilinear lerp of 8 channels: m = t + (b - t) * fx, t = lt + (rt-lt)*fy, ...
__device__ __forceinline__ uint4 lerp8h(uint4 lt, uint4 rt, uint4 lb, uint4 rb,
                                        uint32_t fy2u, uint32_t fx2u) {
    const __half2 fy2 = *reinterpret_cast<__half2*>(&fy2u);
    const __half2 fx2 = *reinterpret_cast<__half2*>(&fx2u);
    uint4 o;
    const uint32_t* pl = (const uint32_t*)&lt;
    const uint32_t* pr = (const uint32_t*)&rt;
    const uint32_t* ql = (const uint32_t*)&lb;
    const uint32_t* qr = (const uint32_t*)&rb;
    uint32_t* po = (uint32_t*)&o;
    #pragma unroll
    for (int w = 0; w < 4; w++) {
        __half2 LT = *reinterpret_cast<const __half2*>(pl + w);
        __half2 RT = *reinterpret_cast<const __half2*>(pr + w);
        __half2 LB = *reinterpret_cast<const __half2*>(ql + w);
        __half2 RB = *reinterpret_cast<const __half2*>(qr + w);
        __half2 t = __hfma2(__hsub2(RT, LT), fy2, LT);
        __half2 b = __hfma2(__hsub2(RB, LB), fy2, LB);
        __half2 m = __hfma2(__hsub2(b, t), fx2, t);
        po[w] = *reinterpret_cast<uint32_t*>(&m);
    }
    return o;
}

// ---------------- x -> fp16 pre-kernel ----------------
__global__ void xh_kernel(const float* __restrict__ x) {
    int i = (blockIdx.x * 256 + threadIdx.x) * 8;
    float4 v0 = *(const float4*)(x + i);
    float4 v1 = *(const float4*)(x + i + 4);
    uint4 o;
    o.x = pack2(v0.x, v0.y);
    o.y = pack2(v0.z, v0.w);
    o.z = pack2(v1.x, v1.y);
    o.w = pack2(v1.z, v1.w);
    *(uint4*)(g_xh + i) = o;
}

// ---------------- W fragment-image pre-kernel (fp16) ----------------
__global__ void wimg_kernel(const float* __restrict__ Wt) {
    int idx = blockIdx.x * 256 + threadIdx.x;   // 0 .. 36*W_CH-1
    int j    = idx & 1;
    int ks   = (idx >> 1) & 1;
    int lane = (idx >> 2) & 31;
    int ft   = (idx >> 7) & 31;
    int k    = idx >> 12;                        // chunk 0..35
    int n    = k >> 2;
    int cc   = k & 3;
    int gq = lane >> 2, tq = lane & 3;
    int f  = ft * 8 + gq;
    int c0 = cc * 32 + ks * 16 + j * 8 + tq * 2;
    float w0 = Wt[((size_t)n * C_ + c0) * F_ + f];
    float w1 = Wt[((size_t)n * C_ + c0 + 1) * F_ + f];
    g_Wimg[idx] = pack2(w0, w1);
}

// ---------------- main fused kernel ----------------
__global__ __launch_bounds__(THREADS, 2)
void deform_mma_kernel(const float* __restrict__ offs,
                       const float* __restrict__ bias,
                       float* __restrict__ out) {
    extern __shared__ float smf[];
    uint32_t* A_buf[2] = { (uint32_t*)smf + A0_OFF, (uint32_t*)smf + A1_OFF };
    uint32_t* W_buf[2] = { (uint32_t*)smf + W0_OFF, (uint32_t*)smf + W1_OFF };
    int4*     s_c4  = (int4*)(smf + C4_OFF);
    uint32_t* s_fy2 = (uint32_t*)smf + FY_OFF;
    uint32_t* s_fx2 = (uint32_t*)smf + FX_OFF;

    const uint32_t w_smem[2] = { smem_u32(W_buf[0]), smem_u32(W_buf[1]) };
    const uint32_t a_smem[2] = { smem_u32(A_buf[0]), smem_u32(A_buf[1]) };

    const int tid  = threadIdx.x;
    const int wid  = tid >> 5;
    const int lane = tid & 31;
    const int wr   = wid >> 2;        // warp row (0..1): m base = wr*32
    const int wc   = wid & 3;         // warp col (0..3): f base = wc*64
    const int gq   = lane >> 2;
    const int tq   = lane & 3;

    // ldmatrix lane offset within the warp's A block (words)
    const int lrow = (lane & 7) + ((lane >> 3) & 1) * 8;
    const int lcol = (lane >> 4) * 4;
    const uint32_t a_frag_off = (uint32_t)(((wr * 32 + lrow) * PADP + lcol) * 4);

    const int blk = blockIdx.x;       // b*64 + h
    const int b   = blk >> 6;
    const int h   = blk & 63;
    const __half* img = g_xh + (size_t)b * H_ * W_ * C_;

    const int c8  = tid & 3;          // 8-channel slice within 32-ch chunk
    const int pix = tid >> 2;         // 0..63

    // ---- start W(stage 0) copy immediately ----
    {
        const uint32_t* wsrc = g_Wimg;
        #pragma unroll
        for (int i = 0; i < 8; i++) {
            int o = i * THREADS + tid;
            cp_async16(w_smem[0] + (uint32_t)o * 16u, wsrc + o * 4);
        }
        cp_commit();
    }

    // ---- precompute corner offsets + fractions for all 9 taps ----
    for (int e = tid; e < N_ * 64; e += THREADS) {
        const int n  = e >> 6;
        const int ww = e & 63;
        const float* orow = offs + (((size_t)blk * 64 + ww) * (2 * N_));
        float cy = (float)(h - 1 + c_iy[n]) + orow[2 * n];
        float cx = (float)(ww - 1 + c_ix[n]) + orow[2 * n + 1];
        cy = fminf(fmaxf(cy, 0.0f), 63.0f);
        cx = fminf(fmaxf(cx, 0.0f), 63.0f);
        float y0f = floorf(cy);
        float x0f = floorf(cx);
        const int y0 = (int)y0f;
        const int x0 = (int)x0f;
        const int y1 = min(y0 + 1, 63);
        const int x1 = min(x0 + 1, 63);
        int4 c4;
        c4.x = (y0 * 64 + x0) << 7;   // lt
        c4.y = (y1 * 64 + x0) << 7;   // rt
        c4.z = (y0 * 64 + x1) << 7;   // lb
        c4.w = (y1 * 64 + x1) << 7;   // rb
        s_c4[e]  = c4;
        const float fy = cy - y0f, fx = cx - x0f;
        s_fy2[e] = pack2(fy, fy);
        s_fx2[e] = pack2(fx, fx);
    }
    __syncthreads();

    float acc[2][8][4];
    #pragma unroll
    for (int mi = 0; mi < 2; mi++)
        #pragma unroll
        for (int ni = 0; ni < 8; ni++)
            #pragma unroll
            for (int r = 0; r < 4; r++) acc[mi][ni][r] = 0.0f;

    // ---- prologue: stage chunks 0,1 (tap 0) into A_buf[0] ----
    {
        const int4 c4 = s_c4[pix];
        const uint32_t fy2 = s_fy2[pix], fx2 = s_fx2[pix];
        #pragma unroll
        for (int cpos = 0; cpos < 2; cpos++) {
            const int c_off = cpos * 32 + c8 * 8;
            uint4 lt = *(const uint4*)(img + c4.x + c_off);
            uint4 rt = *(const uint4*)(img + c4.y + c_off);
            uint4 lb = *(const uint4*)(img + c4.z + c_off);
            uint4 rb = *(const uint4*)(img + c4.w + c_off);
            *(uint4*)(A_buf[0] + pix * PADP + cpos * 16 + c8 * 4) =
                lerp8h(lt, rt, lb, rb, fy2, fx2);
        }
    }

    // ---- main stage loop: 18 stages of K=64 ----
    #pragma unroll 1
    for (int s = 0; s < NSTAGE; s++) {
        cp_wait0();          // my W(s) copies done
        __syncthreads();     // everyone's W(s) done; A(s) visible; buffers reusable

        const int buf  = s & 1;
        const int nbuf = buf ^ 1;
        const bool more = (s + 1 < NSTAGE);

        // W(s+1) into W_buf[nbuf] (safe: all stage-s-1 reads finished at the sync)
        if (more) {
            const uint32_t* wsrc = g_Wimg + (size_t)(2 * (s + 1)) * W_CH;
            #pragma unroll
            for (int i = 0; i < 8; i++) {
                int o = i * THREADS + tid;
                cp_async16(w_smem[nbuf] + (uint32_t)o * 16u, wsrc + o * 4);
            }
            cp_commit();
        }

        int4 c4;
        uint32_t fy2 = 0, fx2 = 0;
        uint4 lt, rt, lb, rb;
        int cbase = 0;
        if (more) {
            const int k0 = 2 * s + 2;           // first chunk staged this stage
            const int e  = (k0 >> 2) * 64 + pix;
            c4  = s_c4[e];
            fy2 = s_fy2[e];
            fx2 = s_fx2[e];
            cbase = (k0 & 3) * 32 + c8 * 8;
            lt = *(const uint4*)(img + c4.x + cbase);
            rt = *(const uint4*)(img + c4.y + cbase);
            lb = *(const uint4*)(img + c4.z + cbase);
            rb = *(const uint4*)(img + c4.w + cbase);
        }

        const uint32_t a_base = a_smem[buf] + a_frag_off;
        const uint32_t* W_s = W_buf[buf];

        // ---- MMA chunk cpos=0 ----
        {
            uint32_t a[2][2][4];
            #pragma unroll
            for (int mi = 0; mi < 2; mi++) {
                ldsm_x4(a[0][mi], a_base + (uint32_t)((mi * 16 * PADP) * 4));
                ldsm_x4(a[1][mi], a_base + (uint32_t)((mi * 16 * PADP + 8) * 4));
            }
            #pragma unroll
            for (int ni = 0; ni < 8; ni++) {
                const int ftl = wc * 8 + ni;
                uint4 bv = *(const uint4*)(W_s + ((ftl * 32) + lane) * 4);
                mma_f16(acc[0][ni], a[0][0], bv.x, bv.y);
                mma_f16(acc[1][ni], a[0][1], bv.x, bv.y);
                mma_f16(acc[0][ni], a[1][0], bv.z, bv.w);
                mma_f16(acc[1][ni], a[1][1], bv.z, bv.w);
            }
        }

        if (more) {
            // finish staging chunk k0; start loads for chunk k0+1
            *(uint4*)(A_buf[nbuf] + pix * PADP + c8 * 4) =
                lerp8h(lt, rt, lb, rb, fy2, fx2);
            const int c_off = cbase + 32;       // (k0+1)&3 = (k0&3)+1 within same tap
            lt = *(const uint4*)(img + c4.x + c_off);
            rt = *(const uint4*)(img + c4.y + c_off);
            lb = *(const uint4*)(img + c4.z + c_off);
            rb = *(const uint4*)(img + c4.w + c_off);
        }

        // ---- MMA chunk cpos=1 ----
        {
            uint32_t a[2][2][4];
            #pragma unroll
            for (int mi = 0; mi < 2; mi++) {
                ldsm_x4(a[0][mi], a_base + (uint32_t)((mi * 16 * PADP + 16) * 4));
                ldsm_x4(a[1][mi], a_base + (uint32_t)((mi * 16 * PADP + 24) * 4));
            }
            #pragma unroll
            for (int ni = 0; ni < 8; ni++) {
                const int ftl = wc * 8 + ni;
                uint4 bv = *(const uint4*)(W_s + W_CH + ((ftl * 32) + lane) * 4);
                mma_f16(acc[0][ni], a[0][0], bv.x, bv.y);
                mma_f16(acc[1][ni], a[0][1], bv.x, bv.y);
                mma_f16(acc[0][ni], a[1][0], bv.z, bv.w);
                mma_f16(acc[1][ni], a[1][1], bv.z, bv.w);
            }
        }

        if (more) {
            *(uint4*)(A_buf[nbuf] + pix * PADP + 16 + c8 * 4) =
                lerp8h(lt, rt, lb, rb, fy2, fx2);
        }
    }

    // ---- epilogue: add bias, store ----
    #pragma unroll
    for (int mi = 0; mi < 2; mi++) {
        const int row0 = wr * 32 + mi * 16 + gq;
        float* o0 = out + ((size_t)blk * 64 + row0) * F_;
        float* o1 = o0 + 8 * F_;
        #pragma unroll
        for (int ni = 0; ni < 8; ni++) {
            const int f = wc * 64 + ni * 8 + tq * 2;
            const float2 bb = *(const float2*)(bias + f);
            float2 r0, r1;
            r0.x = acc[mi][ni][0] + bb.x;
            r0.y = acc[mi][ni][1] + bb.y;
            r1.x = acc[mi][ni][2] + bb.x;
            r1.y = acc[mi][ni][3] + bb.y;
            *(float2*)(o0 + f) = r0;
            *(float2*)(o1 + f) = r1;
        }
    }
}

}  // namespace

extern "C" void kernel_launch(void* const* d_in, const int* in_sizes, int n_in,
                              void* d_out, int out_size) {
    (void)in_sizes; (void)n_in; (void)out_size;
    const float* x    = (const float*)d_in[0];   // (8,64,64,128)
    const float* offs = (const float*)d_in[1];   // (8,64,64,18)
    const float* Wt   = (const float*)d_in[2];   // (9,128,256)
    const float* bias = (const float*)d_in[3];   // (256,)
    float* out = (float*)d_out;                  // (8,64,64,256)

    cudaFuncSetAttribute(deform_mma_kernel,
                         cudaFuncAttributeMaxDynamicSharedMemorySize, SMEM_BYTES);

    xh_kernel<<<(B_ * H_ * W_ * C_) / (256 * 8), 256>>>(x);
    wimg_kernel<<<(36 * W_CH) / 256, 256>>>(Wt);
    deform_mma_kernel<<<B_ * H_, THREADS, SMEM_BYTES>>>(offs, bias, out);
}